// round 10
// baseline (speedup 1.0000x reference)
#include <cuda_runtime.h>
#include <cuda_fp16.h>
#include <cstdint>

#define P_RAYS 2048
#define NSAMP  131072
#define SUPER  128
#define NBLK   (NSAMP / SUPER)   // 1024
#define NTHR   512
#define NCTA   148
#define STILES 4                 // super-tiles (256 points) per sample group

// ---------------- smem layout (bytes) ----------------
#define OFF_W0   0        // weight tiles: 128 rows x 256B, XOR swizzled
#define OFF_W1   32768
#define OFF_W2   65536
#define OFF_WH   98304
#define OFF_X    131072   // input staging: 256 rows x 256B (warp-private 16-row slabs)
#define OFF_FS   196608   // feat_s: 128 rows (also head hidden via OFF_X reuse)
#define OFF_B0   229376   // f16[128]
#define OFF_B1   229632
#define OFF_B2   229888
#define OFF_BH   230144   // f16[128] = [ba0|br0]
#define OFF_WA1  230400   // f16[64]
#define OFF_WR1  230528   // f16[192]
#define OFF_WN   230912   // f32[256]
#define SMEM_TOTAL 231936

__device__ float4 g_samp[NSAMP];   // {alpha, r, g, b}

__device__ __forceinline__ uint32_t smem_u32(const void* p) {
    uint32_t a;
    asm("{ .reg .u64 t; cvta.to.shared.u64 t, %1; cvt.u32.u64 %0, t; }" : "=r"(a) : "l"(p));
    return a;
}
__device__ __forceinline__ uint32_t tadr(int row, int col /*half idx*/) {
    return (uint32_t)(row * 256 + ((((col >> 3) ^ (row & 7))) << 4) + ((col & 7) << 1));
}
__device__ __forceinline__ float lrelu(float x) { return fmaxf(x, 0.1f * x); }
__device__ __forceinline__ __half2 lrelu2h(float x, float y) {
    return __floats2half2_rn(lrelu(x), lrelu(y));
}
__device__ __forceinline__ uint32_t ph2(float x, float y) {
    __half2 h = __floats2half2_rn(x, y);
    return *(uint32_t*)&h;
}
__device__ __forceinline__ void ldsm4(uint32_t addr, uint32_t& r0, uint32_t& r1,
                                      uint32_t& r2, uint32_t& r3) {
    asm volatile("ldmatrix.sync.aligned.m8n8.x4.shared.b16 {%0,%1,%2,%3}, [%4];"
                 : "=r"(r0), "=r"(r1), "=r"(r2), "=r"(r3) : "r"(addr));
}
__device__ __forceinline__ void mma16816(float* c, uint32_t a0, uint32_t a1,
                                         uint32_t a2, uint32_t a3,
                                         uint32_t b0, uint32_t b1) {
    asm volatile(
        "mma.sync.aligned.m16n8k16.row.col.f32.f16.f16.f32 "
        "{%0,%1,%2,%3},{%4,%5,%6,%7},{%8,%9},{%0,%1,%2,%3};"
        : "+f"(c[0]), "+f"(c[1]), "+f"(c[2]), "+f"(c[3])
        : "r"(a0), "r"(a1), "r"(a2), "r"(a3), "r"(b0), "r"(b1));
}
__device__ __forceinline__ void l2hint(const void* p) {
    asm volatile("prefetch.global.L2 [%0];" :: "l"(p));
}

// Layer with A from smem (X staging): warp rows [Rw,Rw+16) x ALL 128 cols.
template <int KS>
__device__ __forceinline__ void layer_smemA(uint32_t aB, uint32_t wB, int Rw,
                                            int lane, float acc[16][4]) {
#pragma unroll
    for (int i = 0; i < 16; i++) {
        acc[i][0] = 0.f; acc[i][1] = 0.f; acc[i][2] = 0.f; acc[i][3] = 0.f;
    }
    const int mat = lane >> 3, rl = lane & 7;
    const int khi = (mat >> 1) & 1;
    const int bnt = (mat >> 1) & 1;
    const int bkh = mat & 1;
    const int ar = Rw + ((mat & 1) << 3) + rl;
    const uint32_t aRow = aB + ar * 256;
    const int ax = ar & 7;
#pragma unroll
    for (int k = 0; k < KS; k++) {
        uint32_t a0, a1, a2, a3;
        ldsm4(aRow + (uint32_t)(((k * 2 + khi) ^ ax) << 4), a0, a1, a2, a3);
#pragma unroll
        for (int n2 = 0; n2 < 8; n2++) {
            const int nr = (n2 * 2 + bnt) * 8 + rl;
            uint32_t b0, b1, b2, b3;
            ldsm4(wB + nr * 256 + (((k * 2 + bkh) ^ (nr & 7)) << 4), b0, b1, b2, b3);
            mma16816(acc[n2 * 2 + 0], a0, a1, a2, a3, b0, b1);
            mma16816(acc[n2 * 2 + 1], a0, a1, a2, a3, b2, b3);
        }
    }
}

// Layer with A resident in registers (packed half2 fragments aF[8][4]).
__device__ __forceinline__ void layer_regA(uint32_t wB, int lane,
                                           const uint32_t aF[8][4], float acc[16][4]) {
#pragma unroll
    for (int i = 0; i < 16; i++) {
        acc[i][0] = 0.f; acc[i][1] = 0.f; acc[i][2] = 0.f; acc[i][3] = 0.f;
    }
    const int mat = lane >> 3, rl = lane & 7;
    const int bnt = (mat >> 1) & 1;
    const int bkh = mat & 1;
#pragma unroll
    for (int k = 0; k < 8; k++) {
#pragma unroll
        for (int n2 = 0; n2 < 8; n2++) {
            const int nr = (n2 * 2 + bnt) * 8 + rl;
            uint32_t b0, b1, b2, b3;
            ldsm4(wB + nr * 256 + (((k * 2 + bkh) ^ (nr & 7)) << 4), b0, b1, b2, b3);
            mma16816(acc[n2 * 2 + 0], aF[k][0], aF[k][1], aF[k][2], aF[k][3], b0, b1);
            mma16816(acc[n2 * 2 + 1], aF[k][0], aF[k][1], aF[k][2], aF[k][3], b2, b3);
        }
    }
}

// bias + lrelu + repack C fragments (acc, ntile n) as next layer's A fragments.
// a0 = (c0,c1) of ntile 2k;  a1 = (c2,c3) of 2k;  a2/a3 = same of ntile 2k+1.
__device__ __forceinline__ void pack_frag(const float acc[16][4], const __half* Bh,
                                          int tg, uint32_t aF[8][4]) {
#pragma unroll
    for (int k = 0; k < 8; k++) {
#pragma unroll
        for (int hf = 0; hf < 2; hf++) {
            const int n = 2 * k + hf;
            float2 bb = __half22float2(*(const __half2*)(Bh + n * 8 + 2 * tg));
            const float* a = acc[n];
            aF[k][2 * hf + 0] = ph2(lrelu(a[0] + bb.x), lrelu(a[1] + bb.y));
            aF[k][2 * hf + 1] = ph2(lrelu(a[2] + bb.x), lrelu(a[3] + bb.y));
        }
    }
}

// Single-tile f16 GEMM for heads: warp rows [R,R+32) x cols [C,C+32).
template <int KS>
__device__ __forceinline__ void layer_mma(uint32_t aB, uint32_t wB, int R, int C,
                                          int lane, float acc[8][4]) {
#pragma unroll
    for (int i = 0; i < 8; i++) {
        acc[i][0] = 0.f; acc[i][1] = 0.f; acc[i][2] = 0.f; acc[i][3] = 0.f;
    }
    const int mat = lane >> 3, rl = lane & 7;
    const int half8 = (mat & 1) << 3;
    const int khi = (mat >> 1) & 1;
    const int bnt = (mat >> 1) & 1;
    const int bkh = mat & 1;
    const int ar0 = R + half8 + rl;
    const uint32_t aRow0 = aB + ar0 * 256;
    const uint32_t aRow1 = aRow0 + 16 * 256;
    const int ax = ar0 & 7;
#pragma unroll 2
    for (int k = 0; k < KS; k++) {
        const uint32_t aoff = (uint32_t)(((k * 2 + khi) ^ ax) << 4);
        uint32_t a00, a01, a02, a03, a10, a11, a12, a13;
        ldsm4(aRow0 + aoff, a00, a01, a02, a03);
        ldsm4(aRow1 + aoff, a10, a11, a12, a13);
#pragma unroll
        for (int n2 = 0; n2 < 2; n2++) {
            const int nr = C + (n2 * 2 + bnt) * 8 + rl;
            uint32_t b0, b1, b2, b3;
            ldsm4(wB + nr * 256 + (((k * 2 + bkh) ^ (nr & 7)) << 4), b0, b1, b2, b3);
            mma16816(acc[n2 * 2 + 0], a00, a01, a02, a03, b0, b1);
            mma16816(acc[n2 * 2 + 1], a00, a01, a02, a03, b2, b3);
            mma16816(acc[4 + n2 * 2 + 0], a10, a11, a12, a13, b0, b1);
            mma16816(acc[4 + n2 * 2 + 1], a10, a11, a12, a13, b2, b3);
        }
    }
}

__global__ __launch_bounds__(NTHR, 1) void nerf_main(
    const float* __restrict__ map_xyz, const float* __restrict__ map_feat,
    const int* __restrict__ ind_voxel, const float* __restrict__ sample_xyz,
    const float* __restrict__ W0, const float* __restrict__ b0,
    const float* __restrict__ W1, const float* __restrict__ b1,
    const float* __restrict__ W2, const float* __restrict__ b2,
    const float* __restrict__ Wa0, const float* __restrict__ ba0,
    const float* __restrict__ Wa1, const float* __restrict__ ba1,
    const float* __restrict__ Wr0, const float* __restrict__ br0,
    const float* __restrict__ Wr1, const float* __restrict__ br1) {
    extern __shared__ char smem[];
    const uint32_t sb = smem_u32(smem);
    const int t = threadIdx.x;
    const int w = t >> 5, lane = t & 31;
    const int Rw = w * 16;                   // this warp's 16-row slab
    const int g = lane >> 2, tg = lane & 3;

    __half* B0h = (__half*)(smem + OFF_B0);
    __half* B1h = (__half*)(smem + OFF_B1);
    __half* B2h = (__half*)(smem + OFF_B2);
    __half* BHh = (__half*)(smem + OFF_BH);
    __half* WA1h = (__half*)(smem + OFF_WA1);
    __half* WR1h = (__half*)(smem + OFF_WR1);
    float* WNf = (float*)(smem + OFF_WN);

    // ---------- weights -> f16 swizzled tiles (once per persistent CTA) ----------
    for (int i = t; i < 8192; i += NTHR)
        ((uint32_t*)(smem + OFF_W0))[i] = 0u;
    __syncthreads();
    for (int e = t; e < 88 * 128; e += NTHR) {
        int k = e >> 7, n = e & 127;
        *(__half*)(smem + OFF_W0 + tadr(n, k)) = __float2half_rn(W0[e]);
    }
    for (int e = t; e < 16384; e += NTHR) {
        int k = e >> 7, n = e & 127;
        uint32_t so = tadr(n, k);
        *(__half*)(smem + OFF_W1 + so) = __float2half_rn(W1[e]);
        *(__half*)(smem + OFF_W2 + so) = __float2half_rn(W2[e]);
    }
    for (int e = t; e < 8192; e += NTHR) {
        int k = e >> 6, n = e & 63;
        *(__half*)(smem + OFF_WH + tadr(n, k)) = __float2half_rn(Wa0[e]);
        *(__half*)(smem + OFF_WH + tadr(n + 64, k)) = __float2half_rn(Wr0[e]);
    }
    if (t < 128) {
        B0h[t] = __float2half_rn(b0[t]);
        B1h[t] = __float2half_rn(b1[t]);
        B2h[t] = __float2half_rn(b2[t]);
    }
    if (t < 64) {
        BHh[t] = __float2half_rn(ba0[t]);
        BHh[64 + t] = __float2half_rn(br0[t]);
        WA1h[t] = __float2half_rn(Wa1[t]);
    }
    if (t < 192) WR1h[t] = __float2half_rn(Wr1[t]);
    __syncthreads();

    float acc[16][4];
    uint32_t aF[8][4];
    const int r = Rw + (lane >> 1);          // gather: 2 lanes per point-row
    const int h = lane & 1;
    const int kk = r & 7;

    for (int bid = blockIdx.x; bid < NBLK; bid += gridDim.x) {
        for (int pp = 0; pp < STILES; pp++) {
            // ---------- gather + posenc -> X (warp-private rows) ----------
            __syncwarp();   // prior ldsm reads of X done before overwrite
            {
                const int gs = bid * SUPER + pp * 32 + (r >> 3);
                const int idx = ind_voxel[gs * 8 + kk];
                char* Xp = smem + OFF_X;
                const float4* f4 = (const float4*)map_feat + (size_t)idx * 16 + h * 8;
#pragma unroll
                for (int j = 0; j < 8; j++) {
                    float4 v = f4[j];
                    int c = h * 32 + j * 4;
                    *(__half2*)(Xp + tadr(r, c)) = __floats2half2_rn(v.x, v.y);
                    *(__half2*)(Xp + tadr(r, c + 2)) = __floats2half2_rn(v.z, v.w);
                }
                float ox = sample_xyz[gs * 3 + 0] - map_xyz[idx * 3 + 0];
                float oy = sample_xyz[gs * 3 + 1] - map_xyz[idx * 3 + 1];
                float oz = sample_xyz[gs * 3 + 2] - map_xyz[idx * 3 + 2];
                if (h == 0) {                // axes 0,1 -> cols 64..79
                    float o2[2] = {ox, oy};
#pragma unroll
                    for (int a = 0; a < 2; a++) {
                        float sn[4], cs[4], fr = 1.f;
#pragma unroll
                        for (int i = 0; i < 4; i++) { __sincosf(o2[a] * fr, &sn[i], &cs[i]); fr *= 2.f; }
                        int c0 = 64 + 8 * a;
                        *(__half2*)(Xp + tadr(r, c0 + 0)) = __floats2half2_rn(sn[0], sn[1]);
                        *(__half2*)(Xp + tadr(r, c0 + 2)) = __floats2half2_rn(sn[2], sn[3]);
                        *(__half2*)(Xp + tadr(r, c0 + 4)) = __floats2half2_rn(cs[0], cs[1]);
                        *(__half2*)(Xp + tadr(r, c0 + 6)) = __floats2half2_rn(cs[2], cs[3]);
                    }
                } else {                     // axis 2 -> cols 80..87, pad 88..95
                    float sn[4], cs[4], fr = 1.f;
#pragma unroll
                    for (int i = 0; i < 4; i++) { __sincosf(oz * fr, &sn[i], &cs[i]); fr *= 2.f; }
                    *(__half2*)(Xp + tadr(r, 80)) = __floats2half2_rn(sn[0], sn[1]);
                    *(__half2*)(Xp + tadr(r, 82)) = __floats2half2_rn(sn[2], sn[3]);
                    *(__half2*)(Xp + tadr(r, 84)) = __floats2half2_rn(cs[0], cs[1]);
                    *(__half2*)(Xp + tadr(r, 86)) = __floats2half2_rn(cs[2], cs[3]);
#pragma unroll
                    for (int c2 = 88; c2 < 96; c2 += 2)
                        *(__half2*)(Xp + tadr(r, c2)) = __floats2half2_rn(0.f, 0.f);
                    float wraw = __expf(-10.f * sqrtf(ox * ox + oy * oy + oz * oz));
                    float ssum = wraw;      // 8 odd lanes of each 16-lane half = 1 sample
                    ssum += __shfl_xor_sync(0xAAAAAAAAu, ssum, 2);
                    ssum += __shfl_xor_sync(0xAAAAAAAAu, ssum, 4);
                    ssum += __shfl_xor_sync(0xAAAAAAAAu, ssum, 8);
                    WNf[r] = wraw / ssum;
                }
            }
            // L2 warm the next tile's gather
            {
                int np = pp + 1, nb = bid;
                if (np == STILES) { np = 0; nb += (int)gridDim.x; }
                if (nb < NBLK) {
                    const int ngs = nb * SUPER + np * 32 + (r >> 3);
                    const int ni = ind_voxel[ngs * 8 + kk];
                    const float4* nf = (const float4*)map_feat + (size_t)ni * 16 + h * 8;
                    l2hint(nf); l2hint(nf + 4);
                    if (h) l2hint(map_xyz + ni * 3);
                }
            }
            __syncwarp();   // X rows visible to whole warp for ldsm

            // ---------- MLP entirely in registers after L0 ----------
            layer_smemA<6>(sb + OFF_X, sb + OFF_W0, Rw, lane, acc);
            pack_frag(acc, B0h, tg, aF);
            layer_regA(sb + OFF_W1, lane, aF, acc);
            pack_frag(acc, B1h, tg, aF);
            layer_regA(sb + OFF_W2, lane, aF, acc);

            // ---------- weighted K-reduce -> FS ----------
            {
                const float wn0 = WNf[Rw + g], wn1 = WNf[Rw + 8 + g];
                const int sA = pp * 32 + (Rw >> 3);   // 2 samples per warp
                char* FSp = smem + OFF_FS;
#pragma unroll
                for (int n = 0; n < 16; n++) {
                    int col = n * 8 + tg * 2;
                    float2 bb = __half22float2(*(__half2*)((char*)B2h + col * 2));
                    float v0 = lrelu(acc[n][0] + bb.x) * wn0;
                    float v1 = lrelu(acc[n][1] + bb.y) * wn0;
                    float v2 = lrelu(acc[n][2] + bb.x) * wn1;
                    float v3 = lrelu(acc[n][3] + bb.y) * wn1;
#pragma unroll
                    for (int off = 4; off <= 16; off <<= 1) {  // sum over 8 neighbors
                        v0 += __shfl_xor_sync(0xFFFFFFFFu, v0, off);
                        v1 += __shfl_xor_sync(0xFFFFFFFFu, v1, off);
                        v2 += __shfl_xor_sync(0xFFFFFFFFu, v2, off);
                        v3 += __shfl_xor_sync(0xFFFFFFFFu, v3, off);
                    }
                    if (g == 0) {
                        *(__half2*)(FSp + tadr(sA, col)) = __floats2half2_rn(v0, v1);
                        *(__half2*)(FSp + tadr(sA + 1, col)) = __floats2half2_rn(v2, v3);
                    }
                }
            }
        }

        __syncthreads();  // all warps' FS writes visible

        // ---------- heads: FS x [Wa0|Wr0] -> X region (hidden) ----------
        {
            const int R2 = (w >> 2) * 32, C2 = (w & 3) * 32;
            float (*acc8)[4] = (float (*)[4])acc;
            layer_mma<8>(sb + OFF_FS, sb + OFF_WH, R2, C2, lane, acc8);
            char* dst = smem + OFF_X;
#pragma unroll
            for (int mt = 0; mt < 2; mt++) {
                int r0 = R2 + mt * 16 + g;
#pragma unroll
                for (int nt = 0; nt < 4; nt++) {
                    int col = C2 + nt * 8 + tg * 2;
                    float2 bh = __half22float2(*(__half2*)((char*)BHh + col * 2));
                    float* a = acc8[mt * 4 + nt];
                    *(__half2*)(dst + tadr(r0, col)) = lrelu2h(a[0] + bh.x, a[1] + bh.y);
                    *(__half2*)(dst + tadr(r0 + 8, col)) = lrelu2h(a[2] + bh.x, a[3] + bh.y);
                }
            }
        }
        __syncthreads();

        // ---------- final projections + sigmoid ----------
        {
            char* Hp = smem + OFF_X;
            if (t < 128) {                         // alpha for sample t
                float a = ba1[0];
#pragma unroll
                for (int m = 0; m < 32; m++) {
                    float2 v = __half22float2(*(__half2*)(Hp + tadr(t, 2 * m)));
                    float2 wv = __half22float2(((__half2*)WA1h)[m]);
                    a += v.x * wv.x + v.y * wv.y;
                }
                ((float*)&g_samp[bid * SUPER + t])[0] = 1.f / (1.f + __expf(-a));
            } else if (t < 256) {                  // rgb for sample t-128
                int s = t - 128;
                float a0 = br1[0], a1 = br1[1], a2 = br1[2];
#pragma unroll
                for (int m = 0; m < 32; m++) {
                    float2 v = __half22float2(*(__half2*)(Hp + tadr(s, 64 + 2 * m)));
                    int j = 2 * m;
                    a0 += v.x * __half2float(WR1h[j * 3 + 0]) + v.y * __half2float(WR1h[j * 3 + 3]);
                    a1 += v.x * __half2float(WR1h[j * 3 + 1]) + v.y * __half2float(WR1h[j * 3 + 4]);
                    a2 += v.x * __half2float(WR1h[j * 3 + 2]) + v.y * __half2float(WR1h[j * 3 + 5]);
                }
                float* gp = (float*)&g_samp[bid * SUPER + s];
                gp[1] = 1.f / (1.f + __expf(-a0));
                gp[2] = 1.f / (1.f + __expf(-a1));
                gp[3] = 1.f / (1.f + __expf(-a2));
            }
        }
        __syncthreads();   // X/FS reads done before next group's gather stores
    }
}

// ---- warp-per-ray volume rendering, log-space prefix scan ----
__global__ __launch_bounds__(256) void nerf_render(const float* __restrict__ dist,
                                                   float* __restrict__ out) {
    int gt = blockIdx.x * blockDim.x + threadIdx.x;
    int ray = gt >> 5, lane = gt & 31;
    if (ray >= P_RAYS) return;
    const float4* gsp = g_samp + ray * 64;
    const float* dp = dist + ray * 64;
    float cr = 0, cg = 0, cb = 0, cd = 0, ca = 0, carry = 0;
#pragma unroll
    for (int hh = 0; hh < 2; hh++) {
        float4 v = gsp[hh * 32 + lane];
        float l = __logf(1.f - v.x + 1e-10f);
        float s = l;
#pragma unroll
        for (int o = 1; o < 32; o <<= 1) {
            float n = __shfl_up_sync(0xFFFFFFFFu, s, o);
            if (lane >= o) s += n;
        }
        float T = __expf(carry + s - l);
        float b = v.x * T;
        float d = 1.0f + 80.0f * dp[hh * 32 + lane] / 64.0f;
        cr += v.y * b; cg += v.z * b; cb += v.w * b; cd += d * b; ca += b;
        carry += __shfl_sync(0xFFFFFFFFu, s, 31);
    }
#pragma unroll
    for (int o = 16; o; o >>= 1) {
        cr += __shfl_down_sync(0xFFFFFFFFu, cr, o);
        cg += __shfl_down_sync(0xFFFFFFFFu, cg, o);
        cb += __shfl_down_sync(0xFFFFFFFFu, cb, o);
        cd += __shfl_down_sync(0xFFFFFFFFu, cd, o);
        ca += __shfl_down_sync(0xFFFFFFFFu, ca, o);
    }
    if (lane == 0) {
        out[ray * 5 + 0] = cr; out[ray * 5 + 1] = cg; out[ray * 5 + 2] = cb;
        out[ray * 5 + 3] = cd; out[ray * 5 + 4] = ca;
    }
}

extern "C" void kernel_launch(void* const* d_in, const int* in_sizes, int n_in,
                              void* d_out, int out_size) {
    cudaFuncSetAttribute(nerf_main, cudaFuncAttributeMaxDynamicSharedMemorySize,
                         SMEM_TOTAL);
    nerf_main<<<NCTA, NTHR, SMEM_TOTAL>>>(
        (const float*)d_in[0], (const float*)d_in[1], (const int*)d_in[2],
        (const float*)d_in[3],
        (const float*)d_in[5], (const float*)d_in[6], (const float*)d_in[7],
        (const float*)d_in[8], (const float*)d_in[9], (const float*)d_in[10],
        (const float*)d_in[11], (const float*)d_in[12], (const float*)d_in[13],
        (const float*)d_in[14], (const float*)d_in[15], (const float*)d_in[16],
        (const float*)d_in[17], (const float*)d_in[18]);
    nerf_render<<<(P_RAYS * 32) / 256, 256>>>((const float*)d_in[4], (float*)d_out);
}

// round 11
// speedup vs baseline: 1.1100x; 1.1100x over previous
#include <cuda_runtime.h>
#include <cuda_fp16.h>
#include <cstdint>

#define P_RAYS 2048
#define NSAMP  131072
#define SUPER  128
#define NBLK   (NSAMP / SUPER)   // 1024
#define NTHR   512
#define NCTA   148
#define PAIRS  4

// ---------------- smem layout (bytes) ----------------
#define OFF_W0   0        // weight tiles: 128 rows x 256B, XOR swizzled
#define OFF_W1   32768
#define OFF_W2   65536
#define OFF_WH   98304
#define OFF_A0   131072   // activations: 256 rows (tile pair), in-place
#define OFF_FS   196608   // feat_s: 128 rows
#define OFF_B0   229376   // f16[128]
#define OFF_B1   229632
#define OFF_B2   229888
#define OFF_BH   230144   // f16[128] = [ba0|br0]
#define OFF_WA1  230400   // f16[64]
#define OFF_WR1  230528   // f16[192]
#define OFF_WN   230912   // f32[256]
#define SMEM_TOTAL 231936

__device__ float4 g_samp[NSAMP];   // {alpha, r, g, b}

__device__ __forceinline__ uint32_t smem_u32(const void* p) {
    uint32_t a;
    asm("{ .reg .u64 t; cvta.to.shared.u64 t, %1; cvt.u32.u64 %0, t; }" : "=r"(a) : "l"(p));
    return a;
}
__device__ __forceinline__ uint32_t tadr(int row, int col /*half idx*/) {
    return (uint32_t)(row * 256 + ((((col >> 3) ^ (row & 7))) << 4) + ((col & 7) << 1));
}
__device__ __forceinline__ float lrelu(float x) { return fmaxf(x, 0.1f * x); }
// packed bias + LeakyReLU: round to f16, add f16 bias, hmax(x, 0.1x)
__device__ __forceinline__ __half2 biaslrelu2(float x, float y, __half2 bb) {
    __half2 v = __hadd2(__floats2half2_rn(x, y), bb);
    return __hmax2(v, __hmul2(v, __floats2half2_rn(0.1f, 0.1f)));
}
__device__ __forceinline__ uint32_t ph2(float x, float y) {
    __half2 h = __floats2half2_rn(x, y);
    return *(uint32_t*)&h;
}
__device__ __forceinline__ uint32_t hadd2u(uint32_t a, uint32_t b) {
    __half2 r = __hadd2(*(__half2*)&a, *(__half2*)&b);
    return *(uint32_t*)&r;
}
__device__ __forceinline__ void ldsm4(uint32_t addr, uint32_t& r0, uint32_t& r1,
                                      uint32_t& r2, uint32_t& r3) {
    asm volatile("ldmatrix.sync.aligned.m8n8.x4.shared.b16 {%0,%1,%2,%3}, [%4];"
                 : "=r"(r0), "=r"(r1), "=r"(r2), "=r"(r3) : "r"(addr));
}
__device__ __forceinline__ void mma16816(float* c, uint32_t a0, uint32_t a1,
                                         uint32_t a2, uint32_t a3,
                                         uint32_t b0, uint32_t b1) {
    asm volatile(
        "mma.sync.aligned.m16n8k16.row.col.f32.f16.f16.f32 "
        "{%0,%1,%2,%3},{%4,%5,%6,%7},{%8,%9},{%0,%1,%2,%3};"
        : "+f"(c[0]), "+f"(c[1]), "+f"(c[2]), "+f"(c[3])
        : "r"(a0), "r"(a1), "r"(a2), "r"(a3), "r"(b0), "r"(b1));
}
__device__ __forceinline__ void rg_bar(int rg) {
    asm volatile("bar.sync %0, %1;" :: "r"(rg + 1), "r"(128) : "memory");
}
__device__ __forceinline__ void l2hint(const void* p) {
    asm volatile("prefetch.global.L2 [%0];" :: "l"(p));
}

// Pair GEMM: warp computes rows [R,R+32) of BOTH tiles x cols [C,C+32).
template <int KS>
__device__ __forceinline__ void layer_mma_pair(uint32_t aB, uint32_t wB, int R, int C,
                                               int lane, float acc[16][4]) {
#pragma unroll
    for (int i = 0; i < 16; i++) {
        acc[i][0] = 0.f; acc[i][1] = 0.f; acc[i][2] = 0.f; acc[i][3] = 0.f;
    }
    const int mat = lane >> 3, rl = lane & 7;
    const int half8 = (mat & 1) << 3;
    const int khi = (mat >> 1) & 1;
    const int bnt = (mat >> 1) & 1;
    const int bkh = mat & 1;
    const int ar0 = R + half8 + rl;
    const uint32_t r0a = aB + ar0 * 256;
    const uint32_t r1a = r0a + 16 * 256;
    const uint32_t r2a = r0a + 128 * 256;
    const uint32_t r3a = r2a + 16 * 256;
    const int ax = ar0 & 7;
#pragma unroll 2
    for (int k = 0; k < KS; k++) {
        const uint32_t aoff = (uint32_t)(((k * 2 + khi) ^ ax) << 4);
        uint32_t p00, p01, p02, p03, p10, p11, p12, p13;
        uint32_t q00, q01, q02, q03, q10, q11, q12, q13;
        ldsm4(r0a + aoff, p00, p01, p02, p03);
        ldsm4(r1a + aoff, p10, p11, p12, p13);
        ldsm4(r2a + aoff, q00, q01, q02, q03);
        ldsm4(r3a + aoff, q10, q11, q12, q13);
#pragma unroll
        for (int n2 = 0; n2 < 2; n2++) {
            const int nr = C + (n2 * 2 + bnt) * 8 + rl;
            uint32_t b0, b1, b2, b3;
            ldsm4(wB + nr * 256 + (((k * 2 + bkh) ^ (nr & 7)) << 4), b0, b1, b2, b3);
            mma16816(acc[n2 * 2 + 0], p00, p01, p02, p03, b0, b1);
            mma16816(acc[n2 * 2 + 1], p00, p01, p02, p03, b2, b3);
            mma16816(acc[4 + n2 * 2 + 0], p10, p11, p12, p13, b0, b1);
            mma16816(acc[4 + n2 * 2 + 1], p10, p11, p12, p13, b2, b3);
            mma16816(acc[8 + n2 * 2 + 0], q00, q01, q02, q03, b0, b1);
            mma16816(acc[8 + n2 * 2 + 1], q00, q01, q02, q03, b2, b3);
            mma16816(acc[12 + n2 * 2 + 0], q10, q11, q12, q13, b0, b1);
            mma16816(acc[12 + n2 * 2 + 1], q10, q11, q12, q13, b2, b3);
        }
    }
}

// Single-tile GEMM (heads): warp rows [R,R+32) x cols [C,C+32).
template <int KS>
__device__ __forceinline__ void layer_mma(uint32_t aB, uint32_t wB, int R, int C,
                                          int lane, float acc[8][4]) {
#pragma unroll
    for (int i = 0; i < 8; i++) {
        acc[i][0] = 0.f; acc[i][1] = 0.f; acc[i][2] = 0.f; acc[i][3] = 0.f;
    }
    const int mat = lane >> 3, rl = lane & 7;
    const int half8 = (mat & 1) << 3;
    const int khi = (mat >> 1) & 1;
    const int bnt = (mat >> 1) & 1;
    const int bkh = mat & 1;
    const int ar0 = R + half8 + rl;
    const uint32_t aRow0 = aB + ar0 * 256;
    const uint32_t aRow1 = aRow0 + 16 * 256;
    const int ax = ar0 & 7;
#pragma unroll 2
    for (int k = 0; k < KS; k++) {
        const uint32_t aoff = (uint32_t)(((k * 2 + khi) ^ ax) << 4);
        uint32_t a00, a01, a02, a03, a10, a11, a12, a13;
        ldsm4(aRow0 + aoff, a00, a01, a02, a03);
        ldsm4(aRow1 + aoff, a10, a11, a12, a13);
#pragma unroll
        for (int n2 = 0; n2 < 2; n2++) {
            const int nr = C + (n2 * 2 + bnt) * 8 + rl;
            uint32_t b0, b1, b2, b3;
            ldsm4(wB + nr * 256 + (((k * 2 + bkh) ^ (nr & 7)) << 4), b0, b1, b2, b3);
            mma16816(acc[n2 * 2 + 0], a00, a01, a02, a03, b0, b1);
            mma16816(acc[n2 * 2 + 1], a00, a01, a02, a03, b2, b3);
            mma16816(acc[4 + n2 * 2 + 0], a10, a11, a12, a13, b0, b1);
            mma16816(acc[4 + n2 * 2 + 1], a10, a11, a12, a13, b2, b3);
        }
    }
}

// Store one gathered point row into A0.
__device__ __forceinline__ void store_rows(char* A0p, int row, float4 v0, float4 v1,
                                           float4 v2, float4 v3, int q, float oax,
                                           float* WNf) {
    const int c = q * 16;
    *(__half2*)(A0p + tadr(row, c + 0)) = __floats2half2_rn(v0.x, v0.y);
    *(__half2*)(A0p + tadr(row, c + 2)) = __floats2half2_rn(v0.z, v0.w);
    *(__half2*)(A0p + tadr(row, c + 4)) = __floats2half2_rn(v1.x, v1.y);
    *(__half2*)(A0p + tadr(row, c + 6)) = __floats2half2_rn(v1.z, v1.w);
    *(__half2*)(A0p + tadr(row, c + 8)) = __floats2half2_rn(v2.x, v2.y);
    *(__half2*)(A0p + tadr(row, c + 10)) = __floats2half2_rn(v2.z, v2.w);
    *(__half2*)(A0p + tadr(row, c + 12)) = __floats2half2_rn(v3.x, v3.y);
    *(__half2*)(A0p + tadr(row, c + 14)) = __floats2half2_rn(v3.z, v3.w);
    float o2 = oax * oax;
    o2 += __shfl_xor_sync(0xFFFFFFFFu, o2, 1);
    o2 += __shfl_xor_sync(0xFFFFFFFFu, o2, 2);   // |offset|^2 on all 4 lanes
    if (q) {
        const int c0 = 64 + 8 * (q - 1);
        float sn[4], cs[4], fr = 1.f;
#pragma unroll
        for (int i = 0; i < 4; i++) { __sincosf(oax * fr, &sn[i], &cs[i]); fr *= 2.f; }
        *(__half2*)(A0p + tadr(row, c0 + 0)) = __floats2half2_rn(sn[0], sn[1]);
        *(__half2*)(A0p + tadr(row, c0 + 2)) = __floats2half2_rn(sn[2], sn[3]);
        *(__half2*)(A0p + tadr(row, c0 + 4)) = __floats2half2_rn(cs[0], cs[1]);
        *(__half2*)(A0p + tadr(row, c0 + 6)) = __floats2half2_rn(cs[2], cs[3]);
    } else {
#pragma unroll
        for (int c2 = 88; c2 < 96; c2 += 2)
            *(__half2*)(A0p + tadr(row, c2)) = __floats2half2_rn(0.f, 0.f);
        float wraw = __expf(-10.f * sqrtf(o2));
        float ssum = wraw;
        ssum += __shfl_xor_sync(0x11111111u, ssum, 4);
        ssum += __shfl_xor_sync(0x11111111u, ssum, 8);
        ssum += __shfl_xor_sync(0x11111111u, ssum, 16);
        WNf[row] = wraw / ssum;
    }
}

__global__ __launch_bounds__(NTHR, 1) void nerf_main(
    const float* __restrict__ map_xyz, const float* __restrict__ map_feat,
    const int* __restrict__ ind_voxel, const float* __restrict__ sample_xyz,
    const float* __restrict__ W0, const float* __restrict__ b0,
    const float* __restrict__ W1, const float* __restrict__ b1,
    const float* __restrict__ W2, const float* __restrict__ b2,
    const float* __restrict__ Wa0, const float* __restrict__ ba0,
    const float* __restrict__ Wa1, const float* __restrict__ ba1,
    const float* __restrict__ Wr0, const float* __restrict__ br0,
    const float* __restrict__ Wr1, const float* __restrict__ br1) {
    extern __shared__ char smem[];
    const uint32_t sb = smem_u32(smem);
    const int t = threadIdx.x;
    const int w = t >> 5, lane = t & 31;
    const int rg = w >> 2;
    const int R = rg * 32;
    const int C = (w & 3) * 32;

    __half* B0h = (__half*)(smem + OFF_B0);
    __half* B1h = (__half*)(smem + OFF_B1);
    __half* B2h = (__half*)(smem + OFF_B2);
    __half* BHh = (__half*)(smem + OFF_BH);
    __half* WA1h = (__half*)(smem + OFF_WA1);
    __half* WR1h = (__half*)(smem + OFF_WR1);
    float* WNf = (float*)(smem + OFF_WN);

    // ---------- weights -> f16 swizzled tiles (once per persistent CTA) ----------
    for (int i = t; i < 8192; i += NTHR)
        ((uint32_t*)(smem + OFF_W0))[i] = 0u;
    __syncthreads();
    for (int e = t; e < 88 * 128; e += NTHR) {
        int k = e >> 7, n = e & 127;
        *(__half*)(smem + OFF_W0 + tadr(n, k)) = __float2half_rn(W0[e]);
    }
    for (int e = t; e < 16384; e += NTHR) {
        int k = e >> 7, n = e & 127;
        uint32_t so = tadr(n, k);
        *(__half*)(smem + OFF_W1 + so) = __float2half_rn(W1[e]);
        *(__half*)(smem + OFF_W2 + so) = __float2half_rn(W2[e]);
    }
    for (int e = t; e < 8192; e += NTHR) {
        int k = e >> 6, n = e & 63;
        *(__half*)(smem + OFF_WH + tadr(n, k)) = __float2half_rn(Wa0[e]);
        *(__half*)(smem + OFF_WH + tadr(n + 64, k)) = __float2half_rn(Wr0[e]);
    }
    if (t < 128) {
        B0h[t] = __float2half_rn(b0[t]);
        B1h[t] = __float2half_rn(b1[t]);
        B2h[t] = __float2half_rn(b2[t]);
    }
    if (t < 64) {
        BHh[t] = __float2half_rn(ba0[t]);
        BHh[64 + t] = __float2half_rn(br0[t]);
        WA1h[t] = __float2half_rn(Wa1[t]);
    }
    if (t < 192) WR1h[t] = __float2half_rn(Wr1[t]);

    // ---------- gather prefetch: first actual pair = (rg skewed) ----------
    const int p = t >> 2, q = t & 3;          // p's row group == rg
    float4 fv[4];
    float oax = 0.f;
    int idx1 = 0;
    {
        const int ap0 = rg & 3;
        const int gs0 = blockIdx.x * SUPER + ap0 * 32 + (p >> 3);
        const int idx = ind_voxel[gs0 * 8 + (p & 7)];
        const float4* f4 = (const float4*)map_feat + (size_t)idx * 16 + q * 4;
        fv[0] = f4[0]; fv[1] = f4[1]; fv[2] = f4[2]; fv[3] = f4[3];
        if (q) oax = sample_xyz[gs0 * 3 + q - 1] - map_xyz[idx * 3 + q - 1];
        const int gs1 = gs0 + 16;
        idx1 = ind_voxel[gs1 * 8 + (p & 7)];
        l2hint((const float4*)map_feat + (size_t)idx1 * 16 + q * 4);
        if (q) l2hint(map_xyz + idx1 * 3);
    }
    __syncthreads();   // weights ready

    float acc[16][4];
    const int g = lane >> 2, tg = lane & 3;

    for (int bid = blockIdx.x; bid < NBLK; bid += gridDim.x) {
        for (int pp = 0; pp < PAIRS; pp++) {
            const int ap = (pp + rg) & 3;     // actual pair for this row group
            // ---------- store gathered pair rows -> A0 ----------
            {
                char* A0p = smem + OFF_A0;
                const int gs1 = bid * SUPER + ap * 32 + 16 + (p >> 3);
                const float4* f4b = (const float4*)map_feat + (size_t)idx1 * 16 + q * 4;
                float4 g0 = f4b[0], g1 = f4b[1], g2 = f4b[2], g3 = f4b[3];
                float oax1 = 0.f;
                if (q) oax1 = sample_xyz[gs1 * 3 + q - 1] - map_xyz[idx1 * 3 + q - 1];
                store_rows(A0p, p, fv[0], fv[1], fv[2], fv[3], q, oax, WNf);
                store_rows(A0p, 128 + p, g0, g1, g2, g3, q, oax1, WNf);
            }
            rg_bar(rg);

            // ---------- prefetch next pair (rg-skewed order) ----------
            {
                int nb = bid, anp;
                if (pp < 3) {
                    anp = (pp + 1 + rg) & 3;
                } else {
                    anp = rg & 3;
                    nb = bid + (int)gridDim.x;
                }
                if (nb < NBLK) {
                    const int gs0 = nb * SUPER + anp * 32 + (p >> 3);
                    const int idx = ind_voxel[gs0 * 8 + (p & 7)];
                    const float4* f4 = (const float4*)map_feat + (size_t)idx * 16 + q * 4;
                    fv[0] = f4[0]; fv[1] = f4[1]; fv[2] = f4[2]; fv[3] = f4[3];
                    if (q) oax = sample_xyz[gs0 * 3 + q - 1] - map_xyz[idx * 3 + q - 1];
                    const int gs1 = gs0 + 16;
                    idx1 = ind_voxel[gs1 * 8 + (p & 7)];
                    l2hint((const float4*)map_feat + (size_t)idx1 * 16 + q * 4);
                    if (q) l2hint(map_xyz + idx1 * 3);
                }
            }

            // ---------- layer 0 (K=96), in-place ----------
            layer_mma_pair<6>(sb + OFF_A0, sb + OFF_W0, R, C, lane, acc);
            rg_bar(rg);   // peer reads of A0 rows done
            {
                char* dst = smem + OFF_A0;
#pragma unroll
                for (int ti = 0; ti < 2; ti++) {
#pragma unroll
                    for (int mt = 0; mt < 2; mt++) {
                        int r0 = ti * 128 + R + mt * 16 + g;
#pragma unroll
                        for (int nt = 0; nt < 4; nt++) {
                            int col = C + nt * 8 + tg * 2;
                            __half2 bb = *(__half2*)((char*)B0h + col * 2);
                            float* a = acc[ti * 8 + mt * 4 + nt];
                            *(__half2*)(dst + tadr(r0, col)) = biaslrelu2(a[0], a[1], bb);
                            *(__half2*)(dst + tadr(r0 + 8, col)) = biaslrelu2(a[2], a[3], bb);
                        }
                    }
                }
            }
            rg_bar(rg);

            // ---------- layer 1, in-place ----------
            layer_mma_pair<8>(sb + OFF_A0, sb + OFF_W1, R, C, lane, acc);
            rg_bar(rg);
            {
                char* dst = smem + OFF_A0;
#pragma unroll
                for (int ti = 0; ti < 2; ti++) {
#pragma unroll
                    for (int mt = 0; mt < 2; mt++) {
                        int r0 = ti * 128 + R + mt * 16 + g;
#pragma unroll
                        for (int nt = 0; nt < 4; nt++) {
                            int col = C + nt * 8 + tg * 2;
                            __half2 bb = *(__half2*)((char*)B1h + col * 2);
                            float* a = acc[ti * 8 + mt * 4 + nt];
                            *(__half2*)(dst + tadr(r0, col)) = biaslrelu2(a[0], a[1], bb);
                            *(__half2*)(dst + tadr(r0 + 8, col)) = biaslrelu2(a[2], a[3], bb);
                        }
                    }
                }
            }
            rg_bar(rg);

            // ---------- layer 2 -> weighted K-reduce -> FS ----------
            layer_mma_pair<8>(sb + OFF_A0, sb + OFF_W2, R, C, lane, acc);
            {
                char* FSp = smem + OFF_FS;
#pragma unroll
                for (int ti = 0; ti < 2; ti++) {
#pragma unroll
                    for (int mt = 0; mt < 2; mt++) {
                        const int Rm = R + mt * 16;
                        const float wn0 = WNf[ti * 128 + Rm + g];
                        const float wn1 = WNf[ti * 128 + Rm + 8 + g];
                        const int sA = ap * 32 + ti * 16 + (Rm >> 3);
#pragma unroll
                        for (int nt = 0; nt < 4; nt++) {
                            int col = C + nt * 8 + tg * 2;
                            float2 bb = __half22float2(*(__half2*)((char*)B2h + col * 2));
                            float* a = acc[ti * 8 + mt * 4 + nt];
                            float v0 = lrelu(a[0] + bb.x) * wn0;
                            float v1 = lrelu(a[1] + bb.y) * wn0;
                            float v2 = lrelu(a[2] + bb.x) * wn1;
                            float v3 = lrelu(a[3] + bb.y) * wn1;
                            // stage 1 (g^1) in fp32
                            v0 += __shfl_xor_sync(0xFFFFFFFFu, v0, 4);
                            v1 += __shfl_xor_sync(0xFFFFFFFFu, v1, 4);
                            v2 += __shfl_xor_sync(0xFFFFFFFFu, v2, 4);
                            v3 += __shfl_xor_sync(0xFFFFFFFFu, v3, 4);
                            // stages 2,3 packed half2
                            uint32_t h01 = ph2(v0, v1), h23 = ph2(v2, v3);
                            h01 = hadd2u(h01, __shfl_xor_sync(0xFFFFFFFFu, h01, 8));
                            h23 = hadd2u(h23, __shfl_xor_sync(0xFFFFFFFFu, h23, 8));
                            h01 = hadd2u(h01, __shfl_xor_sync(0xFFFFFFFFu, h01, 16));
                            h23 = hadd2u(h23, __shfl_xor_sync(0xFFFFFFFFu, h23, 16));
                            if (g == 0) {
                                *(uint32_t*)(FSp + tadr(sA, col)) = h01;
                                *(uint32_t*)(FSp + tadr(sA + 1, col)) = h23;
                            }
                        }
                    }
                }
            }
            rg_bar(rg);   // A0/WN rows reusable for next pair in this row group
        }

        __syncthreads();  // all groups' FS writes visible

        // ---------- heads: FS x [Wa0|Wr0] -> A0 (hidden) ----------
        {
            float (*acc8)[4] = (float (*)[4])acc;
            layer_mma<8>(sb + OFF_FS, sb + OFF_WH, R, C, lane, acc8);
            char* dst = smem + OFF_A0;
#pragma unroll
            for (int mt = 0; mt < 2; mt++) {
                int r0 = R + mt * 16 + g;
#pragma unroll
                for (int nt = 0; nt < 4; nt++) {
                    int col = C + nt * 8 + tg * 2;
                    __half2 bh = *(__half2*)((char*)BHh + col * 2);
                    float* a = acc8[mt * 4 + nt];
                    *(__half2*)(dst + tadr(r0, col)) = biaslrelu2(a[0], a[1], bh);
                    *(__half2*)(dst + tadr(r0 + 8, col)) = biaslrelu2(a[2], a[3], bh);
                }
            }
        }
        __syncthreads();

        // ---------- final projections + sigmoid ----------
        {
            char* Hp = smem + OFF_A0;
            if (t < 128) {                         // alpha for sample t
                float a = ba1[0];
#pragma unroll
                for (int m = 0; m < 32; m++) {
                    float2 v = __half22float2(*(__half2*)(Hp + tadr(t, 2 * m)));
                    float2 wv = __half22float2(((__half2*)WA1h)[m]);
                    a += v.x * wv.x + v.y * wv.y;
                }
                ((float*)&g_samp[bid * SUPER + t])[0] = 1.f / (1.f + __expf(-a));
            } else if (t < 256) {                  // rgb for sample t-128
                int s = t - 128;
                float a0 = br1[0], a1 = br1[1], a2 = br1[2];
#pragma unroll
                for (int m = 0; m < 32; m++) {
                    float2 v = __half22float2(*(__half2*)(Hp + tadr(s, 64 + 2 * m)));
                    int j = 2 * m;
                    a0 += v.x * __half2float(WR1h[j * 3 + 0]) + v.y * __half2float(WR1h[j * 3 + 3]);
                    a1 += v.x * __half2float(WR1h[j * 3 + 1]) + v.y * __half2float(WR1h[j * 3 + 4]);
                    a2 += v.x * __half2float(WR1h[j * 3 + 2]) + v.y * __half2float(WR1h[j * 3 + 5]);
                }
                float* gp = (float*)&g_samp[bid * SUPER + s];
                gp[1] = 1.f / (1.f + __expf(-a0));
                gp[2] = 1.f / (1.f + __expf(-a1));
                gp[3] = 1.f / (1.f + __expf(-a2));
            }
        }
        __syncthreads();   // A0 reads done before next group's gather stores
    }
}

// ---- warp-per-ray volume rendering, log-space prefix scan ----
__global__ __launch_bounds__(256) void nerf_render(const float* __restrict__ dist,
                                                   float* __restrict__ out) {
    int gt = blockIdx.x * blockDim.x + threadIdx.x;
    int ray = gt >> 5, lane = gt & 31;
    if (ray >= P_RAYS) return;
    const float4* gsp = g_samp + ray * 64;
    const float* dp = dist + ray * 64;
    float cr = 0, cg = 0, cb = 0, cd = 0, ca = 0, carry = 0;
#pragma unroll
    for (int hh = 0; hh < 2; hh++) {
        float4 v = gsp[hh * 32 + lane];
        float l = __logf(1.f - v.x + 1e-10f);
        float s = l;
#pragma unroll
        for (int o = 1; o < 32; o <<= 1) {
            float n = __shfl_up_sync(0xFFFFFFFFu, s, o);
            if (lane >= o) s += n;
        }
        float T = __expf(carry + s - l);
        float b = v.x * T;
        float d = 1.0f + 80.0f * dp[hh * 32 + lane] / 64.0f;
        cr += v.y * b; cg += v.z * b; cb += v.w * b; cd += d * b; ca += b;
        carry += __shfl_sync(0xFFFFFFFFu, s, 31);
    }
#pragma unroll
    for (int o = 16; o; o >>= 1) {
        cr += __shfl_down_sync(0xFFFFFFFFu, cr, o);
        cg += __shfl_down_sync(0xFFFFFFFFu, cg, o);
        cb += __shfl_down_sync(0xFFFFFFFFu, cb, o);
        cd += __shfl_down_sync(0xFFFFFFFFu, cd, o);
        ca += __shfl_down_sync(0xFFFFFFFFu, ca, o);
    }
    if (lane == 0) {
        out[ray * 5 + 0] = cr; out[ray * 5 + 1] = cg; out[ray * 5 + 2] = cb;
        out[ray * 5 + 3] = cd; out[ray * 5 + 4] = ca;
    }
}

extern "C" void kernel_launch(void* const* d_in, const int* in_sizes, int n_in,
                              void* d_out, int out_size) {
    cudaFuncSetAttribute(nerf_main, cudaFuncAttributeMaxDynamicSharedMemorySize,
                         SMEM_TOTAL);
    nerf_main<<<NCTA, NTHR, SMEM_TOTAL>>>(
        (const float*)d_in[0], (const float*)d_in[1], (const int*)d_in[2],
        (const float*)d_in[3],
        (const float*)d_in[5], (const float*)d_in[6], (const float*)d_in[7],
        (const float*)d_in[8], (const float*)d_in[9], (const float*)d_in[10],
        (const float*)d_in[11], (const float*)d_in[12], (const float*)d_in[13],
        (const float*)d_in[14], (const float*)d_in[15], (const float*)d_in[16],
        (const float*)d_in[17], (const float*)d_in[18]);
    nerf_render<<<(P_RAYS * 32) / 256, 256>>>((const float*)d_in[4], (float*)d_out);
}